// round 1
// baseline (speedup 1.0000x reference)
#include <cuda_runtime.h>

// Problem constants
#define B_ 4
#define N_ 4096
#define D_ 512
#define K_ 32

#define TILES 32            // N_/128
#define PAIRS 528           // TILES*(TILES+1)/2

// Scratch (device globals — no runtime allocation allowed)
__device__ float g_xn[B_ * N_ * D_];                     // 32 MB normalized input
__device__ float g_sim[(size_t)B_ * N_ * N_];            // 268 MB similarity matrix

// ---------------------------------------------------------------------------
// Kernel 1: row L2-normalization.  One 128-thread block per row (512 floats).
// ---------------------------------------------------------------------------
__global__ void __launch_bounds__(128) normalize_kernel(const float* __restrict__ x) {
    int row = blockIdx.x;                       // 0 .. B*N-1
    const float* xr = x + (size_t)row * D_;
    float* outr = g_xn + (size_t)row * D_;
    int t = threadIdx.x;

    float4 v = ((const float4*)xr)[t];          // 128 threads * 4 = 512
    float ss = v.x * v.x + v.y * v.y + v.z * v.z + v.w * v.w;

    #pragma unroll
    for (int o = 16; o; o >>= 1) ss += __shfl_xor_sync(0xffffffffu, ss, o);

    __shared__ float wsum[4];
    if ((t & 31) == 0) wsum[t >> 5] = ss;
    __syncthreads();
    float total = wsum[0] + wsum[1] + wsum[2] + wsum[3];

    float norm = sqrtf(total);
    float scale = 1.0f / fmaxf(norm, 1e-12f);

    float4 o4;
    o4.x = v.x * scale; o4.y = v.y * scale; o4.z = v.z * scale; o4.w = v.w * scale;
    ((float4*)outr)[t] = o4;
}

// ---------------------------------------------------------------------------
// Kernel 2: symmetric batched GEMM  S = Xn * Xn^T  (fp32, 128x128x8 tiles,
// 256 threads, 8x8 register micro-tile, double-buffered smem).
// Only upper-triangular tile pairs are computed; mirror tiles are bit-copies,
// guaranteeing sim[i][j] == sim[j][i] bitwise (needed for deterministic
// atomic symmetrization later).
// ---------------------------------------------------------------------------
__global__ void __launch_bounds__(256) gemm_sym_kernel() {
    int bidx = blockIdx.x;
    int b = bidx / PAIRS;
    int u = bidx % PAIRS;
    int ti = 0;
    while (u >= TILES - ti) { u -= TILES - ti; ti++; }
    int tj = ti + u;                            // tj >= ti

    const float* Ag = g_xn + ((size_t)b * N_ + (size_t)ti * 128) * D_;
    const float* Bg = g_xn + ((size_t)b * N_ + (size_t)tj * 128) * D_;

    __shared__ float As[2][8][128];
    __shared__ float Bs[2][8][128];

    int t = threadIdx.x;
    int tx = t & 15;            // column group
    int ty = t >> 4;            // row group
    int lrow = t >> 1;          // 0..127  (load mapping)
    int lseg = (t & 1) * 4;     // 0 or 4

    float acc[8][8];
    #pragma unroll
    for (int r = 0; r < 8; r++)
        #pragma unroll
        for (int c = 0; c < 8; c++) acc[r][c] = 0.0f;

    // Prologue: stage 0
    float4 a4 = *(const float4*)(Ag + (size_t)lrow * D_ + lseg);
    float4 b4 = *(const float4*)(Bg + (size_t)lrow * D_ + lseg);
    As[0][lseg + 0][lrow] = a4.x; As[0][lseg + 1][lrow] = a4.y;
    As[0][lseg + 2][lrow] = a4.z; As[0][lseg + 3][lrow] = a4.w;
    Bs[0][lseg + 0][lrow] = b4.x; Bs[0][lseg + 1][lrow] = b4.y;
    Bs[0][lseg + 2][lrow] = b4.z; Bs[0][lseg + 3][lrow] = b4.w;
    __syncthreads();

    const int NK = D_ / 8;      // 64 k-stages
    for (int kt = 0; kt < NK; kt++) {
        int cur = kt & 1;
        if (kt + 1 < NK) {
            int k0 = (kt + 1) * 8;
            a4 = *(const float4*)(Ag + (size_t)lrow * D_ + k0 + lseg);
            b4 = *(const float4*)(Bg + (size_t)lrow * D_ + k0 + lseg);
        }
        #pragma unroll
        for (int kk = 0; kk < 8; kk++) {
            float ar[8], br[8];
            #pragma unroll
            for (int r = 0; r < 8; r++) ar[r] = As[cur][kk][ty * 8 + r];
            #pragma unroll
            for (int c = 0; c < 8; c++) br[c] = Bs[cur][kk][tx * 8 + c];
            #pragma unroll
            for (int r = 0; r < 8; r++)
                #pragma unroll
                for (int c = 0; c < 8; c++)
                    acc[r][c] = fmaf(ar[r], br[c], acc[r][c]);
        }
        if (kt + 1 < NK) {
            int nxt = cur ^ 1;
            As[nxt][lseg + 0][lrow] = a4.x; As[nxt][lseg + 1][lrow] = a4.y;
            As[nxt][lseg + 2][lrow] = a4.z; As[nxt][lseg + 3][lrow] = a4.w;
            Bs[nxt][lseg + 0][lrow] = b4.x; Bs[nxt][lseg + 1][lrow] = b4.y;
            Bs[nxt][lseg + 2][lrow] = b4.z; Bs[nxt][lseg + 3][lrow] = b4.w;
            __syncthreads();
        }
    }

    float* C = g_sim + (size_t)b * N_ * N_;
    int gi0 = ti * 128 + ty * 8;
    int gj0 = tj * 128 + tx * 8;

    #pragma unroll
    for (int r = 0; r < 8; r++) {
        float4 s0, s1;
        s0.x = acc[r][0]; s0.y = acc[r][1]; s0.z = acc[r][2]; s0.w = acc[r][3];
        s1.x = acc[r][4]; s1.y = acc[r][5]; s1.z = acc[r][6]; s1.w = acc[r][7];
        *(float4*)(C + (size_t)(gi0 + r) * N_ + gj0)     = s0;
        *(float4*)(C + (size_t)(gi0 + r) * N_ + gj0 + 4) = s1;
    }
    if (ti != tj) {
        // Mirror tile (bit-exact transpose copy)
        #pragma unroll
        for (int c = 0; c < 8; c++)
            #pragma unroll
            for (int r = 0; r < 8; r++)
                C[(size_t)(gj0 + c) * N_ + gi0 + r] = acc[r][c];
    }
}

// ---------------------------------------------------------------------------
// Kernel 3: per-row top-32 (value, index) + symmetric atomic scatter.
// One 256-thread block per row. Row kept in registers (16/thread).
// 32 rounds of block argmax (warp shuffle + 8-wide final), tie-break to
// lowest index to match jax.lax.top_k semantics.
// ---------------------------------------------------------------------------
__global__ void __launch_bounds__(256) topk_scatter_kernel(float* __restrict__ out) {
    int row = blockIdx.x;
    int b = row >> 12;              // / 4096
    int i = row & (N_ - 1);
    const float* srow = g_sim + (size_t)b * N_ * N_ + (size_t)i * N_;
    int t = threadIdx.x;
    int lane = t & 31, warp = t >> 5;

    float v[16];
    #pragma unroll
    for (int q = 0; q < 16; q++) v[q] = srow[q * 256 + t];

    __shared__ float wV[8];
    __shared__ int   wI[8];
    __shared__ float bcastV;
    __shared__ int   bcastI;
    __shared__ float topV[K_];
    __shared__ int   topI[K_];

    const float NEG_INF = __int_as_float(0xff800000);

    for (int r = 0; r < K_; r++) {
        // thread-local argmax (ascending q => lowest index wins ties)
        float bv = v[0]; int bq = 0;
        #pragma unroll
        for (int q = 1; q < 16; q++)
            if (v[q] > bv) { bv = v[q]; bq = q; }
        int bix = bq * 256 + t;

        // warp argmax (tie -> lower index)
        #pragma unroll
        for (int o = 16; o; o >>= 1) {
            float ov = __shfl_xor_sync(0xffffffffu, bv, o);
            int   oi = __shfl_xor_sync(0xffffffffu, bix, o);
            if (ov > bv || (ov == bv && oi < bix)) { bv = ov; bix = oi; }
        }
        if (lane == 0) { wV[warp] = bv; wI[warp] = bix; }
        __syncthreads();

        if (t == 0) {
            float fv = wV[0]; int fi = wI[0];
            #pragma unroll
            for (int w = 1; w < 8; w++) {
                float ov = wV[w]; int oi = wI[w];
                if (ov > fv || (ov == fv && oi < fi)) { fv = ov; fi = oi; }
            }
            bcastV = fv; bcastI = fi;
            topV[r] = fv; topI[r] = fi;
        }
        __syncthreads();

        int wi = bcastI;
        if ((wi & 255) == t) v[wi >> 8] = NEG_INF;   // remove winner
        __syncthreads();
    }

    if (t < K_) {
        float val = 0.5f * topV[t];
        int j = topI[t];
        float* ob = out + (size_t)b * N_ * N_;
        atomicAdd(ob + (size_t)i * N_ + j, val);
        atomicAdd(ob + (size_t)j * N_ + i, val);
    }
}

// ---------------------------------------------------------------------------
extern "C" void kernel_launch(void* const* d_in, const int* in_sizes, int n_in,
                              void* d_out, int out_size) {
    const float* x = (const float*)d_in[0];
    float* out = (float*)d_out;

    cudaMemsetAsync(out, 0, (size_t)out_size * sizeof(float));
    normalize_kernel<<<B_ * N_, 128>>>(x);
    gemm_sym_kernel<<<B_ * PAIRS, 256>>>();
    topk_scatter_kernel<<<B_ * N_, 256>>>(out);
}

// round 4
// speedup vs baseline: 1.2062x; 1.2062x over previous
#include <cuda_runtime.h>
#include <cuda_bf16.h>
#include <cstdint>

// Problem constants
#define B_ 4
#define N_ 4096
#define D_ 512
#define K_ 32
#define TILES 32            // N_/128
#define PAIRS 528           // TILES*(TILES+1)/2

// Scratch (device globals — no runtime allocation allowed)
__device__ __align__(128) __nv_bfloat16 g_h[(size_t)B_ * N_ * D_];    // 16 MB
__device__ __align__(128) __nv_bfloat16 g_m[(size_t)B_ * N_ * D_];    // 16 MB
__device__ __align__(128) __nv_bfloat16 g_l[(size_t)B_ * N_ * D_];    // 16 MB
__device__ __align__(128) float g_sim[(size_t)B_ * N_ * N_];          // 268 MB

// ---------------------------------------------------------------------------
// Portable PTX helpers (compute_103-safe: no tcgen05 / no 'a'-features)
// ---------------------------------------------------------------------------
__device__ __forceinline__ uint32_t smem_u32(const void* p) {
    uint32_t a;
    asm("{ .reg .u64 t; cvta.to.shared.u64 t, %1; cvt.u32.u64 %0, t; }"
        : "=r"(a) : "l"(p));
    return a;
}

#define SWZ(off) ((off) ^ (((off) >> 3) & 0x70))

#define CP_ASYNC16(dst_u32, src_ptr) \
    asm volatile("cp.async.cg.shared.global [%0], [%1], 16;" \
                 :: "r"(dst_u32), "l"(src_ptr) : "memory")
#define CP_COMMIT() asm volatile("cp.async.commit_group;" ::: "memory")
#define CP_WAIT(n)  asm volatile("cp.async.wait_group %0;" :: "n"(n) : "memory")

#define LDSM_X4(r0, r1, r2, r3, addr) \
    asm volatile("ldmatrix.sync.aligned.m8n8.x4.shared.b16 {%0,%1,%2,%3}, [%4];" \
                 : "=r"(r0), "=r"(r1), "=r"(r2), "=r"(r3) : "r"(addr))

#define MMA16816(c, a, b) \
    asm volatile("mma.sync.aligned.m16n8k16.row.col.f32.bf16.bf16.f32 " \
                 "{%0,%1,%2,%3}, {%4,%5,%6,%7}, {%8,%9}, {%0,%1,%2,%3};" \
                 : "+f"((c)[0]), "+f"((c)[1]), "+f"((c)[2]), "+f"((c)[3]) \
                 : "r"((a)[0]), "r"((a)[1]), "r"((a)[2]), "r"((a)[3]), \
                   "r"((b)[0]), "r"((b)[1]))

// ---------------------------------------------------------------------------
// Kernel 1: row L2-normalization + bf16 3-limb split (h + m + l ~ 24 bits).
// Each extraction residual (x - h) is exact in fp32 (Sterbenz), so
// h + m + l approximates x_norm to ~2^-27 relative.
// ---------------------------------------------------------------------------
__global__ void __launch_bounds__(128) normalize_kernel(const float* __restrict__ x) {
    int row = blockIdx.x;
    const float* xr = x + (size_t)row * D_;
    int t = threadIdx.x;

    float4 v = ((const float4*)xr)[t];
    float ss = v.x * v.x + v.y * v.y + v.z * v.z + v.w * v.w;
    #pragma unroll
    for (int o = 16; o; o >>= 1) ss += __shfl_xor_sync(0xffffffffu, ss, o);

    __shared__ float wsum[4];
    if ((t & 31) == 0) wsum[t >> 5] = ss;
    __syncthreads();
    float total = wsum[0] + wsum[1] + wsum[2] + wsum[3];
    float scale = 1.0f / fmaxf(sqrtf(total), 1e-12f);

    float xn[4] = {v.x * scale, v.y * scale, v.z * scale, v.w * scale};
    unsigned short hs[4], ms[4], ls[4];
    #pragma unroll
    for (int q = 0; q < 4; q++) {
        __nv_bfloat16 h = __float2bfloat16(xn[q]);
        float r1 = xn[q] - __bfloat162float(h);
        __nv_bfloat16 m = __float2bfloat16(r1);
        float r2 = r1 - __bfloat162float(m);
        __nv_bfloat16 l = __float2bfloat16(r2);
        hs[q] = __bfloat16_as_ushort(h);
        ms[q] = __bfloat16_as_ushort(m);
        ls[q] = __bfloat16_as_ushort(l);
    }
    uint2 hp, mp, lp;
    hp.x = (uint32_t)hs[0] | ((uint32_t)hs[1] << 16);
    hp.y = (uint32_t)hs[2] | ((uint32_t)hs[3] << 16);
    mp.x = (uint32_t)ms[0] | ((uint32_t)ms[1] << 16);
    mp.y = (uint32_t)ms[2] | ((uint32_t)ms[3] << 16);
    lp.x = (uint32_t)ls[0] | ((uint32_t)ls[1] << 16);
    lp.y = (uint32_t)ls[2] | ((uint32_t)ls[3] << 16);
    ((uint2*)(g_h + (size_t)row * D_))[t] = hp;
    ((uint2*)(g_m + (size_t)row * D_))[t] = mp;
    ((uint2*)(g_l + (size_t)row * D_))[t] = lp;
}

// ---------------------------------------------------------------------------
// Kernel 2: symmetric batched GEMM, bf16 3-limb 6-pass on mma.sync (HMMA).
// Passes: hh + hm + mh + mm + hl + lh  (dropped terms <= 2^-27).
// 128x128 CTA tile, 8 warps (2 x 4), warp tile 64x32, K-chunks of 64,
// cp.async double-buffered SW128-swizzled smem (6 limb tiles per chunk).
// ---------------------------------------------------------------------------
#define CHUNK_BYTES 16384                 // 128 rows x 64 bf16 (128B/row)
#define BUF_BYTES   (6 * CHUNK_BYTES)     // Ah, Am, Al, Bh, Bm, Bl = 96 KB
#define SMEM_TOTAL  (2 * BUF_BYTES)       // 192 KB; transpose area reuses it

__global__ void __launch_bounds__(256, 1) gemm_hmma_kernel() {
    extern __shared__ __align__(1024) char smem[];
    uint32_t sbase = smem_u32(smem);
    int tid = threadIdx.x;
    int wid = tid >> 5;
    int lane = tid & 31;

    int bidx = blockIdx.x;
    int b = bidx / PAIRS;
    int u = bidx % PAIRS;
    int ti = 0;
    while (u >= TILES - ti) { u -= TILES - ti; ti++; }
    int tj = ti + u;                      // tj >= ti

    size_t aoff = ((size_t)b * N_ + (size_t)ti * 128) * D_;
    size_t boff = ((size_t)b * N_ + (size_t)tj * 128) * D_;
    const __nv_bfloat16* srcs[6] = {
        g_h + aoff, g_m + aoff, g_l + aoff,     // A limbs
        g_h + boff, g_m + boff, g_l + boff      // B limbs
    };

    int wm = wid & 1;                     // 2 warps in M (64 rows each)
    int wn = wid >> 1;                    // 4 warps in N (32 cols each)

    float acc[4][4][4];
    #pragma unroll
    for (int mt = 0; mt < 4; mt++)
        #pragma unroll
        for (int nt = 0; nt < 4; nt++)
            #pragma unroll
            for (int q = 0; q < 4; q++) acc[mt][nt][q] = 0.0f;

    // ---- chunk loader: gmem -> swizzled smem via cp.async (96 KB) ----
    auto load_chunk = [&](int kc, int buf) {
        uint32_t bufoff = sbase + buf * BUF_BYTES;
        #pragma unroll
        for (int tile = 0; tile < 6; ++tile) {
            #pragma unroll
            for (int q = 0; q < 4; ++q) {
                int uu = q * 256 + tid;           // 0..1023
                int row = uu >> 3;
                int seg = uu & 7;                 // 16B segment within 128B row
                const __nv_bfloat16* src = srcs[tile] + (size_t)row * D_ + kc * 64 + seg * 8;
                uint32_t dst = bufoff + tile * CHUNK_BYTES + SWZ(row * 128 + seg * 16);
                CP_ASYNC16(dst, src);
            }
        }
    };

    int lr = lane & 15;
    int lc = (lane >> 4) * 16;            // byte column half

    auto compute_chunk = [&](int buf) {
        uint32_t aH = sbase + buf * BUF_BYTES;
        uint32_t aM = aH + CHUNK_BYTES;
        uint32_t aL = aH + 2 * CHUNK_BYTES;
        uint32_t bH = aH + 3 * CHUNK_BYTES;
        uint32_t bM = aH + 4 * CHUNK_BYTES;
        uint32_t bL = aH + 5 * CHUNK_BYTES;
        #pragma unroll
        for (int ks = 0; ks < 4; ++ks) {
            int kb = ks * 32;
            uint32_t ah[4][4], am[4][4], al[4][4];
            uint32_t bh[4][2], bm[4][2], bl[4][2];
            #pragma unroll
            for (int mt = 0; mt < 4; ++mt) {
                int row = wm * 64 + mt * 16 + lr;
                uint32_t off = SWZ(row * 128 + kb + lc);
                LDSM_X4(ah[mt][0], ah[mt][1], ah[mt][2], ah[mt][3], aH + off);
                LDSM_X4(am[mt][0], am[mt][1], am[mt][2], am[mt][3], aM + off);
                LDSM_X4(al[mt][0], al[mt][1], al[mt][2], al[mt][3], aL + off);
            }
            #pragma unroll
            for (int h = 0; h < 2; ++h) {
                int row = wn * 32 + h * 16 + lr;
                uint32_t off = SWZ(row * 128 + kb + lc);
                uint32_t r0, r1, r2, r3;
                LDSM_X4(r0, r1, r2, r3, bH + off);
                bh[2 * h + 0][0] = r0; bh[2 * h + 0][1] = r2;
                bh[2 * h + 1][0] = r1; bh[2 * h + 1][1] = r3;
                LDSM_X4(r0, r1, r2, r3, bM + off);
                bm[2 * h + 0][0] = r0; bm[2 * h + 0][1] = r2;
                bm[2 * h + 1][0] = r1; bm[2 * h + 1][1] = r3;
                LDSM_X4(r0, r1, r2, r3, bL + off);
                bl[2 * h + 0][0] = r0; bl[2 * h + 0][1] = r2;
                bl[2 * h + 1][0] = r1; bl[2 * h + 1][1] = r3;
            }
            #pragma unroll
            for (int mt = 0; mt < 4; ++mt)
                #pragma unroll
                for (int nt = 0; nt < 4; ++nt) {
                    MMA16816(acc[mt][nt], ah[mt], bh[nt]);   // hh
                    MMA16816(acc[mt][nt], ah[mt], bm[nt]);   // hm
                    MMA16816(acc[mt][nt], am[mt], bh[nt]);   // mh
                    MMA16816(acc[mt][nt], am[mt], bm[nt]);   // mm
                    MMA16816(acc[mt][nt], ah[mt], bl[nt]);   // hl
                    MMA16816(acc[mt][nt], al[mt], bh[nt]);   // lh
                }
        }
    };

    // ---- pipelined main loop over 8 K-chunks ----
    const int NCHUNK = D_ / 64;
    load_chunk(0, 0); CP_COMMIT();
    for (int kc = 0; kc < NCHUNK; ++kc) {
        if (kc + 1 < NCHUNK) {
            load_chunk(kc + 1, (kc + 1) & 1); CP_COMMIT();
            CP_WAIT(1);
        } else {
            CP_WAIT(0);
        }
        __syncthreads();
        compute_chunk(kc & 1);
        __syncthreads();                  // before next load overwrites other buf
    }

    // ---- epilogue: direct tile (coalesced float2 per fragment row) ----
    float* C = g_sim + (size_t)b * N_ * N_;
    int r0 = ti * 128 + wm * 64 + (lane >> 2);
    int c0 = tj * 128 + wn * 32 + (lane & 3) * 2;
    #pragma unroll
    for (int mt = 0; mt < 4; ++mt)
        #pragma unroll
        for (int nt = 0; nt < 4; ++nt) {
            float2 v01 = make_float2(acc[mt][nt][0], acc[mt][nt][1]);
            float2 v23 = make_float2(acc[mt][nt][2], acc[mt][nt][3]);
            *(float2*)(C + (size_t)(r0 + mt * 16) * N_ + c0 + nt * 8)     = v01;
            *(float2*)(C + (size_t)(r0 + mt * 16 + 8) * N_ + c0 + nt * 8) = v23;
        }

    // ---- mirror tile via smem transpose (coalesced write-out) ----
    if (ti != tj) {
        float* T = (float*)smem;          // [128][132] floats (67584 B)
        int rl = wm * 64 + (lane >> 2);
        int cl = wn * 32 + (lane & 3) * 2;
        #pragma unroll
        for (int mt = 0; mt < 4; ++mt)
            #pragma unroll
            for (int nt = 0; nt < 4; ++nt) {
                int rr = rl + mt * 16;
                int cc = cl + nt * 8;
                T[(size_t)(cc + 0) * 132 + rr]     = acc[mt][nt][0];
                T[(size_t)(cc + 1) * 132 + rr]     = acc[mt][nt][1];
                T[(size_t)(cc + 0) * 132 + rr + 8] = acc[mt][nt][2];
                T[(size_t)(cc + 1) * 132 + rr + 8] = acc[mt][nt][3];
            }
        __syncthreads();
        int jb = tj * 128, ib = ti * 128;
        #pragma unroll
        for (int q = 0; q < 16; ++q) {
            int uu = q * 256 + tid;       // 0..4095
            int r = uu >> 5;
            int c4 = uu & 31;
            float4 v = *(float4*)&T[(size_t)r * 132 + c4 * 4];
            *(float4*)(C + (size_t)(jb + r) * N_ + ib + c4 * 4) = v;
        }
    }
}

// ---------------------------------------------------------------------------
// Kernel 3: per-row top-32 + symmetric atomic scatter.
// Phase 1: each warp takes 512 elements, extracts its own top-32 with
// shuffle-only reductions (no block barriers). Phase 2: warp 0 merges the
// 8x32 candidates. Tie-break everywhere: higher value, then lower index
// (matches jax.lax.top_k selection set).
// ---------------------------------------------------------------------------
__global__ void __launch_bounds__(256) topk_scatter_kernel(float* __restrict__ out) {
    int row = blockIdx.x;
    int b = row >> 12;
    int i = row & (N_ - 1);
    const float* srow = g_sim + (size_t)b * N_ * N_ + (size_t)i * N_;
    int t = threadIdx.x;
    int lane = t & 31, warp = t >> 5;

    const float NEG_INF = __int_as_float(0xff800000);

    // element index = warp*512 + q*32 + lane  (coalesced loads)
    float v[16];
    #pragma unroll
    for (int q = 0; q < 16; q++) v[q] = srow[warp * 512 + q * 32 + lane];

    __shared__ float cV[256];
    __shared__ int   cI[256];

    // ---- phase 1: per-warp top-32 (no block syncs) ----
    for (int r = 0; r < K_; r++) {
        float bv = v[0]; int bq = 0;
        #pragma unroll
        for (int q = 1; q < 16; q++)
            if (v[q] > bv) { bv = v[q]; bq = q; }     // ascending q => lowest idx on tie
        int bix = warp * 512 + bq * 32 + lane;

        #pragma unroll
        for (int o = 16; o; o >>= 1) {
            float ov = __shfl_xor_sync(0xffffffffu, bv, o);
            int   oi = __shfl_xor_sync(0xffffffffu, bix, o);
            if (ov > bv || (ov == bv && oi < bix)) { bv = ov; bix = oi; }
        }
        if (lane == 0) { cV[warp * 32 + r] = bv; cI[warp * 32 + r] = bix; }
        // invalidate winner (warp-uniform bix)
        if ((bix & 31) == lane) v[(bix >> 5) & 15] = NEG_INF;
    }
    __syncthreads();

    // ---- phase 2: warp 0 merges 256 candidates -> top-32 + scatter ----
    __shared__ float sV[K_];
    __shared__ int   sI[K_];
    if (warp == 0) {
        float cv[8]; int ci[8];
        #pragma unroll
        for (int j = 0; j < 8; j++) { cv[j] = cV[j * 32 + lane]; ci[j] = cI[j * 32 + lane]; }

        for (int r = 0; r < K_; r++) {
            float bv = cv[0]; int bi = ci[0];
            #pragma unroll
            for (int j = 1; j < 8; j++)
                if (cv[j] > bv || (cv[j] == bv && ci[j] < bi)) { bv = cv[j]; bi = ci[j]; }

            #pragma unroll
            for (int o = 16; o; o >>= 1) {
                float ov = __shfl_xor_sync(0xffffffffu, bv, o);
                int   oi = __shfl_xor_sync(0xffffffffu, bi, o);
                if (ov > bv || (ov == bv && oi < bi)) { bv = ov; bi = oi; }
            }
            if (lane == 0) { sV[r] = bv; sI[r] = bi; }
            // invalidate (global element indices are unique)
            #pragma unroll
            for (int j = 0; j < 8; j++)
                if (ci[j] == bi) cv[j] = NEG_INF;
        }
    }
    __syncthreads();

    if (t < K_) {
        float val = 0.5f * sV[t];
        int j = sI[t];
        float* ob = out + (size_t)b * N_ * N_;
        atomicAdd(ob + (size_t)i * N_ + j, val);
        atomicAdd(ob + (size_t)j * N_ + i, val);
    }
}

// ---------------------------------------------------------------------------
extern "C" void kernel_launch(void* const* d_in, const int* in_sizes, int n_in,
                              void* d_out, int out_size) {
    const float* x = (const float*)d_in[0];
    float* out = (float*)d_out;

    cudaFuncSetAttribute(gemm_hmma_kernel,
                         cudaFuncAttributeMaxDynamicSharedMemorySize, SMEM_TOTAL);

    cudaMemsetAsync(out, 0, (size_t)out_size * sizeof(float));
    normalize_kernel<<<B_ * N_, 128>>>(x);
    gemm_hmma_kernel<<<B_ * PAIRS, 256, SMEM_TOTAL>>>();
    topk_scatter_kernel<<<B_ * N_, 256>>>(out);
}

// round 5
// speedup vs baseline: 1.2172x; 1.0091x over previous
#include <cuda_runtime.h>
#include <cuda_bf16.h>
#include <cstdint>

// Problem constants
#define B_ 4
#define N_ 4096
#define D_ 512
#define K_ 32
#define TILES 32            // N_/128
#define PAIRS 528           // TILES*(TILES+1)/2

// Scratch (device globals — no runtime allocation allowed)
__device__ __align__(128) __nv_bfloat16 g_h[(size_t)B_ * N_ * D_];    // 16 MB
__device__ __align__(128) __nv_bfloat16 g_m[(size_t)B_ * N_ * D_];    // 16 MB
__device__ __align__(128) __nv_bfloat16 g_l[(size_t)B_ * N_ * D_];    // 16 MB
__device__ __align__(128) float g_sim[(size_t)B_ * N_ * N_];          // 268 MB

// ---------------------------------------------------------------------------
// Portable PTX helpers (compute_103-safe: no tcgen05 / no 'a'-features)
// ---------------------------------------------------------------------------
__device__ __forceinline__ uint32_t smem_u32(const void* p) {
    uint32_t a;
    asm("{ .reg .u64 t; cvta.to.shared.u64 t, %1; cvt.u32.u64 %0, t; }"
        : "=r"(a) : "l"(p));
    return a;
}

#define SWZ(off) ((off) ^ (((off) >> 3) & 0x70))

#define CP_ASYNC16(dst_u32, src_ptr) \
    asm volatile("cp.async.cg.shared.global [%0], [%1], 16;" \
                 :: "r"(dst_u32), "l"(src_ptr) : "memory")
#define CP_COMMIT() asm volatile("cp.async.commit_group;" ::: "memory")
#define CP_WAIT(n)  asm volatile("cp.async.wait_group %0;" :: "n"(n) : "memory")

#define LDSM_X4(r0, r1, r2, r3, addr) \
    asm volatile("ldmatrix.sync.aligned.m8n8.x4.shared.b16 {%0,%1,%2,%3}, [%4];" \
                 : "=r"(r0), "=r"(r1), "=r"(r2), "=r"(r3) : "r"(addr))

#define MMA16816(c, a, b) \
    asm volatile("mma.sync.aligned.m16n8k16.row.col.f32.bf16.bf16.f32 " \
                 "{%0,%1,%2,%3}, {%4,%5,%6,%7}, {%8,%9}, {%0,%1,%2,%3};" \
                 : "+f"((c)[0]), "+f"((c)[1]), "+f"((c)[2]), "+f"((c)[3]) \
                 : "r"((a)[0]), "r"((a)[1]), "r"((a)[2]), "r"((a)[3]), \
                   "r"((b)[0]), "r"((b)[1]))

// ---------------------------------------------------------------------------
// Kernel 1: row L2-normalization + bf16 3-limb split (h + m + l ~ 24 bits).
// ---------------------------------------------------------------------------
__global__ void __launch_bounds__(128) normalize_kernel(const float* __restrict__ x) {
    int row = blockIdx.x;
    const float* xr = x + (size_t)row * D_;
    int t = threadIdx.x;

    float4 v = ((const float4*)xr)[t];
    float ss = v.x * v.x + v.y * v.y + v.z * v.z + v.w * v.w;
    #pragma unroll
    for (int o = 16; o; o >>= 1) ss += __shfl_xor_sync(0xffffffffu, ss, o);

    __shared__ float wsum[4];
    if ((t & 31) == 0) wsum[t >> 5] = ss;
    __syncthreads();
    float total = wsum[0] + wsum[1] + wsum[2] + wsum[3];
    float scale = 1.0f / fmaxf(sqrtf(total), 1e-12f);

    float xn[4] = {v.x * scale, v.y * scale, v.z * scale, v.w * scale};
    unsigned short hs[4], ms[4], ls[4];
    #pragma unroll
    for (int q = 0; q < 4; q++) {
        __nv_bfloat16 h = __float2bfloat16(xn[q]);
        float r1 = xn[q] - __bfloat162float(h);
        __nv_bfloat16 m = __float2bfloat16(r1);
        float r2 = r1 - __bfloat162float(m);
        __nv_bfloat16 l = __float2bfloat16(r2);
        hs[q] = __bfloat16_as_ushort(h);
        ms[q] = __bfloat16_as_ushort(m);
        ls[q] = __bfloat16_as_ushort(l);
    }
    uint2 hp, mp, lp;
    hp.x = (uint32_t)hs[0] | ((uint32_t)hs[1] << 16);
    hp.y = (uint32_t)hs[2] | ((uint32_t)hs[3] << 16);
    mp.x = (uint32_t)ms[0] | ((uint32_t)ms[1] << 16);
    mp.y = (uint32_t)ms[2] | ((uint32_t)ms[3] << 16);
    lp.x = (uint32_t)ls[0] | ((uint32_t)ls[1] << 16);
    lp.y = (uint32_t)ls[2] | ((uint32_t)ls[3] << 16);
    ((uint2*)(g_h + (size_t)row * D_))[t] = hp;
    ((uint2*)(g_m + (size_t)row * D_))[t] = mp;
    ((uint2*)(g_l + (size_t)row * D_))[t] = lp;
}

// ---------------------------------------------------------------------------
// Kernel 2: symmetric batched GEMM, bf16 3-limb 6-pass on mma.sync (HMMA).
// 128x128 CTA tile, 16 warps (4 x 4), warp tile 32x32, K-chunks of 64,
// cp.async double-buffered SW128-swizzled smem. Pass/k order identical to
// R4 so g_sim is bitwise unchanged.
// ---------------------------------------------------------------------------
#define CHUNK_BYTES 16384                 // 128 rows x 64 bf16 (128B/row)
#define BUF_BYTES   (6 * CHUNK_BYTES)     // Ah, Am, Al, Bh, Bm, Bl = 96 KB
#define SMEM_TOTAL  (2 * BUF_BYTES)       // 192 KB; transpose area reuses it

__global__ void __launch_bounds__(512, 1) gemm_hmma_kernel() {
    extern __shared__ __align__(1024) char smem[];
    uint32_t sbase = smem_u32(smem);
    int tid = threadIdx.x;
    int wid = tid >> 5;
    int lane = tid & 31;

    int bidx = blockIdx.x;
    int b = bidx / PAIRS;
    int u = bidx % PAIRS;
    int ti = 0;
    while (u >= TILES - ti) { u -= TILES - ti; ti++; }
    int tj = ti + u;                      // tj >= ti

    size_t aoff = ((size_t)b * N_ + (size_t)ti * 128) * D_;
    size_t boff = ((size_t)b * N_ + (size_t)tj * 128) * D_;
    const __nv_bfloat16* srcs[6] = {
        g_h + aoff, g_m + aoff, g_l + aoff,     // A limbs
        g_h + boff, g_m + boff, g_l + boff      // B limbs
    };

    int wm = wid & 3;                     // 4 warps in M (32 rows each)
    int wn = wid >> 2;                    // 4 warps in N (32 cols each)

    float acc[2][4][4];
    #pragma unroll
    for (int mt = 0; mt < 2; mt++)
        #pragma unroll
        for (int nt = 0; nt < 4; nt++)
            #pragma unroll
            for (int q = 0; q < 4; q++) acc[mt][nt][q] = 0.0f;

    // ---- chunk loader: gmem -> swizzled smem via cp.async (96 KB) ----
    auto load_chunk = [&](int kc, int buf) {
        uint32_t bufoff = sbase + buf * BUF_BYTES;
        #pragma unroll
        for (int tile = 0; tile < 6; ++tile) {
            #pragma unroll
            for (int q = 0; q < 2; ++q) {
                int uu = q * 512 + tid;           // 0..1023
                int row = uu >> 3;
                int seg = uu & 7;                 // 16B segment within 128B row
                const __nv_bfloat16* src = srcs[tile] + (size_t)row * D_ + kc * 64 + seg * 8;
                uint32_t dst = bufoff + tile * CHUNK_BYTES + SWZ(row * 128 + seg * 16);
                CP_ASYNC16(dst, src);
            }
        }
    };

    int lr = lane & 15;
    int lc = (lane >> 4) * 16;            // byte column half

    auto compute_chunk = [&](int buf) {
        uint32_t aH = sbase + buf * BUF_BYTES;
        uint32_t aM = aH + CHUNK_BYTES;
        uint32_t aL = aH + 2 * CHUNK_BYTES;
        uint32_t bH = aH + 3 * CHUNK_BYTES;
        uint32_t bM = aH + 4 * CHUNK_BYTES;
        uint32_t bL = aH + 5 * CHUNK_BYTES;
        #pragma unroll
        for (int ks = 0; ks < 4; ++ks) {
            int kb = ks * 32;
            uint32_t ah[2][4], am[2][4], al[2][4];
            uint32_t bh[4][2], bm[4][2], bl[4][2];
            #pragma unroll
            for (int mt = 0; mt < 2; ++mt) {
                int row = wm * 32 + mt * 16 + lr;
                uint32_t off = SWZ(row * 128 + kb + lc);
                LDSM_X4(ah[mt][0], ah[mt][1], ah[mt][2], ah[mt][3], aH + off);
                LDSM_X4(am[mt][0], am[mt][1], am[mt][2], am[mt][3], aM + off);
                LDSM_X4(al[mt][0], al[mt][1], al[mt][2], al[mt][3], aL + off);
            }
            #pragma unroll
            for (int h = 0; h < 2; ++h) {
                int row = wn * 32 + h * 16 + lr;
                uint32_t off = SWZ(row * 128 + kb + lc);
                uint32_t r0, r1, r2, r3;
                LDSM_X4(r0, r1, r2, r3, bH + off);
                bh[2 * h + 0][0] = r0; bh[2 * h + 0][1] = r2;
                bh[2 * h + 1][0] = r1; bh[2 * h + 1][1] = r3;
                LDSM_X4(r0, r1, r2, r3, bM + off);
                bm[2 * h + 0][0] = r0; bm[2 * h + 0][1] = r2;
                bm[2 * h + 1][0] = r1; bm[2 * h + 1][1] = r3;
                LDSM_X4(r0, r1, r2, r3, bL + off);
                bl[2 * h + 0][0] = r0; bl[2 * h + 0][1] = r2;
                bl[2 * h + 1][0] = r1; bl[2 * h + 1][1] = r3;
            }
            #pragma unroll
            for (int mt = 0; mt < 2; ++mt)
                #pragma unroll
                for (int nt = 0; nt < 4; ++nt) {
                    MMA16816(acc[mt][nt], ah[mt], bh[nt]);   // hh
                    MMA16816(acc[mt][nt], ah[mt], bm[nt]);   // hm
                    MMA16816(acc[mt][nt], am[mt], bh[nt]);   // mh
                    MMA16816(acc[mt][nt], am[mt], bm[nt]);   // mm
                    MMA16816(acc[mt][nt], ah[mt], bl[nt]);   // hl
                    MMA16816(acc[mt][nt], al[mt], bh[nt]);   // lh
                }
        }
    };

    // ---- pipelined main loop over 8 K-chunks ----
    const int NCHUNK = D_ / 64;
    load_chunk(0, 0); CP_COMMIT();
    for (int kc = 0; kc < NCHUNK; ++kc) {
        if (kc + 1 < NCHUNK) {
            load_chunk(kc + 1, (kc + 1) & 1); CP_COMMIT();
            CP_WAIT(1);
        } else {
            CP_WAIT(0);
        }
        __syncthreads();
        compute_chunk(kc & 1);
        __syncthreads();                  // before next load overwrites other buf
    }

    // ---- epilogue: direct tile (coalesced float2 per fragment row) ----
    float* C = g_sim + (size_t)b * N_ * N_;
    int r0 = ti * 128 + wm * 32 + (lane >> 2);
    int c0 = tj * 128 + wn * 32 + (lane & 3) * 2;
    #pragma unroll
    for (int mt = 0; mt < 2; ++mt)
        #pragma unroll
        for (int nt = 0; nt < 4; ++nt) {
            float2 v01 = make_float2(acc[mt][nt][0], acc[mt][nt][1]);
            float2 v23 = make_float2(acc[mt][nt][2], acc[mt][nt][3]);
            *(float2*)(C + (size_t)(r0 + mt * 16) * N_ + c0 + nt * 8)     = v01;
            *(float2*)(C + (size_t)(r0 + mt * 16 + 8) * N_ + c0 + nt * 8) = v23;
        }

    // ---- mirror tile via smem transpose (coalesced write-out) ----
    if (ti != tj) {
        float* T = (float*)smem;          // [128][132] floats (67584 B)
        int rl = wm * 32 + (lane >> 2);
        int cl = wn * 32 + (lane & 3) * 2;
        #pragma unroll
        for (int mt = 0; mt < 2; ++mt)
            #pragma unroll
            for (int nt = 0; nt < 4; ++nt) {
                int rr = rl + mt * 16;
                int cc = cl + nt * 8;
                T[(size_t)(cc + 0) * 132 + rr]     = acc[mt][nt][0];
                T[(size_t)(cc + 1) * 132 + rr]     = acc[mt][nt][1];
                T[(size_t)(cc + 0) * 132 + rr + 8] = acc[mt][nt][2];
                T[(size_t)(cc + 1) * 132 + rr + 8] = acc[mt][nt][3];
            }
        __syncthreads();
        int jb = tj * 128, ib = ti * 128;
        #pragma unroll
        for (int q = 0; q < 8; ++q) {
            int uu = q * 512 + tid;       // 0..4095
            int r = uu >> 5;
            int c4 = uu & 31;
            float4 v = *(float4*)&T[(size_t)r * 132 + c4 * 4];
            *(float4*)(C + (size_t)(jb + r) * N_ + ib + c4 * 4) = v;
        }
    }
}

// ---------------------------------------------------------------------------
// Kernel 3: per-row top-32 + symmetric atomic scatter (unchanged from R4).
// ---------------------------------------------------------------------------
__global__ void __launch_bounds__(256) topk_scatter_kernel(float* __restrict__ out) {
    int row = blockIdx.x;
    int b = row >> 12;
    int i = row & (N_ - 1);
    const float* srow = g_sim + (size_t)b * N_ * N_ + (size_t)i * N_;
    int t = threadIdx.x;
    int lane = t & 31, warp = t >> 5;

    const float NEG_INF = __int_as_float(0xff800000);

    float v[16];
    #pragma unroll
    for (int q = 0; q < 16; q++) v[q] = srow[warp * 512 + q * 32 + lane];

    __shared__ float cV[256];
    __shared__ int   cI[256];

    // ---- phase 1: per-warp top-32 (no block syncs) ----
    for (int r = 0; r < K_; r++) {
        float bv = v[0]; int bq = 0;
        #pragma unroll
        for (int q = 1; q < 16; q++)
            if (v[q] > bv) { bv = v[q]; bq = q; }
        int bix = warp * 512 + bq * 32 + lane;

        #pragma unroll
        for (int o = 16; o; o >>= 1) {
            float ov = __shfl_xor_sync(0xffffffffu, bv, o);
            int   oi = __shfl_xor_sync(0xffffffffu, bix, o);
            if (ov > bv || (ov == bv && oi < bix)) { bv = ov; bix = oi; }
        }
        if (lane == 0) { cV[warp * 32 + r] = bv; cI[warp * 32 + r] = bix; }
        if ((bix & 31) == lane) v[(bix >> 5) & 15] = NEG_INF;
    }
    __syncthreads();

    // ---- phase 2: warp 0 merges 256 candidates -> top-32 + scatter ----
    __shared__ float sV[K_];
    __shared__ int   sI[K_];
    if (warp == 0) {
        float cv[8]; int ci[8];
        #pragma unroll
        for (int j = 0; j < 8; j++) { cv[j] = cV[j * 32 + lane]; ci[j] = cI[j * 32 + lane]; }

        for (int r = 0; r < K_; r++) {
            float bv = cv[0]; int bi = ci[0];
            #pragma unroll
            for (int j = 1; j < 8; j++)
                if (cv[j] > bv || (cv[j] == bv && ci[j] < bi)) { bv = cv[j]; bi = ci[j]; }

            #pragma unroll
            for (int o = 16; o; o >>= 1) {
                float ov = __shfl_xor_sync(0xffffffffu, bv, o);
                int   oi = __shfl_xor_sync(0xffffffffu, bi, o);
                if (ov > bv || (ov == bv && oi < bi)) { bv = ov; bi = oi; }
            }
            if (lane == 0) { sV[r] = bv; sI[r] = bi; }
            #pragma unroll
            for (int j = 0; j < 8; j++)
                if (ci[j] == bi) cv[j] = NEG_INF;
        }
    }
    __syncthreads();

    if (t < K_) {
        float val = 0.5f * sV[t];
        int j = sI[t];
        float* ob = out + (size_t)b * N_ * N_;
        atomicAdd(ob + (size_t)i * N_ + j, val);
        atomicAdd(ob + (size_t)j * N_ + i, val);
    }
}

// ---------------------------------------------------------------------------
extern "C" void kernel_launch(void* const* d_in, const int* in_sizes, int n_in,
                              void* d_out, int out_size) {
    const float* x = (const float*)d_in[0];
    float* out = (float*)d_out;

    cudaFuncSetAttribute(gemm_hmma_kernel,
                         cudaFuncAttributeMaxDynamicSharedMemorySize, SMEM_TOTAL);

    cudaMemsetAsync(out, 0, (size_t)out_size * sizeof(float));
    normalize_kernel<<<B_ * N_, 128>>>(x);
    gemm_hmma_kernel<<<B_ * PAIRS, 512, SMEM_TOTAL>>>();
    topk_scatter_kernel<<<B_ * N_, 256>>>(out);
}

// round 6
// speedup vs baseline: 1.4845x; 1.2196x over previous
#include <cuda_runtime.h>
#include <cuda_fp16.h>
#include <cstdint>

// Problem constants
#define B_ 4
#define N_ 4096
#define D_ 512
#define K_ 32
#define TILES 32            // N_/128
#define PAIRS 528           // TILES*(TILES+1)/2

// Scratch (device globals — no runtime allocation allowed)
__device__ __align__(128) __half g_h[(size_t)B_ * N_ * D_];           // 16 MB
__device__ __align__(128) __half g_l[(size_t)B_ * N_ * D_];           // 16 MB
__device__ __align__(128) float g_sim[(size_t)B_ * N_ * N_];          // 268 MB

// ---------------------------------------------------------------------------
// Portable PTX helpers (compute_103-safe)
// ---------------------------------------------------------------------------
__device__ __forceinline__ uint32_t smem_u32(const void* p) {
    uint32_t a;
    asm("{ .reg .u64 t; cvta.to.shared.u64 t, %1; cvt.u32.u64 %0, t; }"
        : "=r"(a) : "l"(p));
    return a;
}

#define SWZ(off) ((off) ^ (((off) >> 3) & 0x70))

#define CP_ASYNC16(dst_u32, src_ptr) \
    asm volatile("cp.async.cg.shared.global [%0], [%1], 16;" \
                 :: "r"(dst_u32), "l"(src_ptr) : "memory")
#define CP_COMMIT() asm volatile("cp.async.commit_group;" ::: "memory")
#define CP_WAIT(n)  asm volatile("cp.async.wait_group %0;" :: "n"(n) : "memory")

#define LDSM_X4(r0, r1, r2, r3, addr) \
    asm volatile("ldmatrix.sync.aligned.m8n8.x4.shared.b16 {%0,%1,%2,%3}, [%4];" \
                 : "=r"(r0), "=r"(r1), "=r"(r2), "=r"(r3) : "r"(addr))

#define MMA16816F16(c, a, b) \
    asm volatile("mma.sync.aligned.m16n8k16.row.col.f32.f16.f16.f32 " \
                 "{%0,%1,%2,%3}, {%4,%5,%6,%7}, {%8,%9}, {%0,%1,%2,%3};" \
                 : "+f"((c)[0]), "+f"((c)[1]), "+f"((c)[2]), "+f"((c)[3]) \
                 : "r"((a)[0]), "r"((a)[1]), "r"((a)[2]), "r"((a)[3]), \
                   "r"((b)[0]), "r"((b)[1]))

// ---------------------------------------------------------------------------
// Kernel 1: row L2-normalization + fp16 2-limb split (h + l ~ 22+ bits).
// |x_norm| <= 1 so fp16 range is safe; residual l may be subnormal (tensor
// cores consume fp16 subnormals without flushing).
// ---------------------------------------------------------------------------
__global__ void __launch_bounds__(128) normalize_kernel(const float* __restrict__ x) {
    int row = blockIdx.x;
    const float* xr = x + (size_t)row * D_;
    int t = threadIdx.x;

    float4 v = ((const float4*)xr)[t];
    float ss = v.x * v.x + v.y * v.y + v.z * v.z + v.w * v.w;
    #pragma unroll
    for (int o = 16; o; o >>= 1) ss += __shfl_xor_sync(0xffffffffu, ss, o);

    __shared__ float wsum[4];
    if ((t & 31) == 0) wsum[t >> 5] = ss;
    __syncthreads();
    float total = wsum[0] + wsum[1] + wsum[2] + wsum[3];
    float scale = 1.0f / fmaxf(sqrtf(total), 1e-12f);

    float xn[4] = {v.x * scale, v.y * scale, v.z * scale, v.w * scale};
    unsigned short hs[4], ls[4];
    #pragma unroll
    for (int q = 0; q < 4; q++) {
        __half h = __float2half_rn(xn[q]);
        float r1 = xn[q] - __half2float(h);
        __half l = __float2half_rn(r1);
        hs[q] = __half_as_ushort(h);
        ls[q] = __half_as_ushort(l);
    }
    uint2 hp, lp;
    hp.x = (uint32_t)hs[0] | ((uint32_t)hs[1] << 16);
    hp.y = (uint32_t)hs[2] | ((uint32_t)hs[3] << 16);
    lp.x = (uint32_t)ls[0] | ((uint32_t)ls[1] << 16);
    lp.y = (uint32_t)ls[2] | ((uint32_t)ls[3] << 16);
    ((uint2*)(g_h + (size_t)row * D_))[t] = hp;
    ((uint2*)(g_l + (size_t)row * D_))[t] = lp;
}

// ---------------------------------------------------------------------------
// Kernel 2: symmetric batched GEMM, fp16 2-limb 3-pass on mma.sync (HMMA).
// Passes: hh + hl + lh (dropped ll ~ 2^-22 relative -> below fp32 noise).
// 128x128 CTA tile, 16 warps (4 x 4), warp tile 32x32, K-chunks of 64,
// cp.async double-buffered SW128-swizzled smem (4 limb tiles per chunk).
// ---------------------------------------------------------------------------
#define CHUNK_BYTES 16384                 // 128 rows x 64 fp16 (128B/row)
#define BUF_BYTES   (4 * CHUNK_BYTES)     // Ah, Al, Bh, Bl = 64 KB
#define SMEM_TOTAL  (2 * BUF_BYTES)       // 128 KB; transpose area reuses it

__global__ void __launch_bounds__(512, 1) gemm_hmma_kernel() {
    extern __shared__ __align__(1024) char smem[];
    uint32_t sbase = smem_u32(smem);
    int tid = threadIdx.x;
    int wid = tid >> 5;
    int lane = tid & 31;

    int bidx = blockIdx.x;
    int b = bidx / PAIRS;
    int u = bidx % PAIRS;
    int ti = 0;
    while (u >= TILES - ti) { u -= TILES - ti; ti++; }
    int tj = ti + u;                      // tj >= ti

    size_t aoff = ((size_t)b * N_ + (size_t)ti * 128) * D_;
    size_t boff = ((size_t)b * N_ + (size_t)tj * 128) * D_;
    const __half* srcs[4] = {
        g_h + aoff, g_l + aoff,           // A limbs
        g_h + boff, g_l + boff            // B limbs
    };

    int wm = wid & 3;                     // 4 warps in M (32 rows each)
    int wn = wid >> 2;                    // 4 warps in N (32 cols each)

    float acc[2][4][4];
    #pragma unroll
    for (int mt = 0; mt < 2; mt++)
        #pragma unroll
        for (int nt = 0; nt < 4; nt++)
            #pragma unroll
            for (int q = 0; q < 4; q++) acc[mt][nt][q] = 0.0f;

    // ---- chunk loader: gmem -> swizzled smem via cp.async (64 KB) ----
    auto load_chunk = [&](int kc, int buf) {
        uint32_t bufoff = sbase + buf * BUF_BYTES;
        #pragma unroll
        for (int tile = 0; tile < 4; ++tile) {
            #pragma unroll
            for (int q = 0; q < 2; ++q) {
                int uu = q * 512 + tid;           // 0..1023
                int row = uu >> 3;
                int seg = uu & 7;                 // 16B segment within 128B row
                const __half* src = srcs[tile] + (size_t)row * D_ + kc * 64 + seg * 8;
                uint32_t dst = bufoff + tile * CHUNK_BYTES + SWZ(row * 128 + seg * 16);
                CP_ASYNC16(dst, src);
            }
        }
    };

    int lr = lane & 15;
    int lc = (lane >> 4) * 16;            // byte column half

    auto compute_chunk = [&](int buf) {
        uint32_t aH = sbase + buf * BUF_BYTES;
        uint32_t aL = aH + CHUNK_BYTES;
        uint32_t bH = aH + 2 * CHUNK_BYTES;
        uint32_t bL = aH + 3 * CHUNK_BYTES;
        #pragma unroll
        for (int ks = 0; ks < 4; ++ks) {
            int kb = ks * 32;
            uint32_t ah[2][4], al[2][4];
            uint32_t bh[4][2], bl[4][2];
            #pragma unroll
            for (int mt = 0; mt < 2; ++mt) {
                int row = wm * 32 + mt * 16 + lr;
                uint32_t off = SWZ(row * 128 + kb + lc);
                LDSM_X4(ah[mt][0], ah[mt][1], ah[mt][2], ah[mt][3], aH + off);
                LDSM_X4(al[mt][0], al[mt][1], al[mt][2], al[mt][3], aL + off);
            }
            #pragma unroll
            for (int h = 0; h < 2; ++h) {
                int row = wn * 32 + h * 16 + lr;
                uint32_t off = SWZ(row * 128 + kb + lc);
                uint32_t r0, r1, r2, r3;
                LDSM_X4(r0, r1, r2, r3, bH + off);
                bh[2 * h + 0][0] = r0; bh[2 * h + 0][1] = r2;
                bh[2 * h + 1][0] = r1; bh[2 * h + 1][1] = r3;
                LDSM_X4(r0, r1, r2, r3, bL + off);
                bl[2 * h + 0][0] = r0; bl[2 * h + 0][1] = r2;
                bl[2 * h + 1][0] = r1; bl[2 * h + 1][1] = r3;
            }
            #pragma unroll
            for (int mt = 0; mt < 2; ++mt)
                #pragma unroll
                for (int nt = 0; nt < 4; ++nt) {
                    MMA16816F16(acc[mt][nt], ah[mt], bh[nt]);   // hh
                    MMA16816F16(acc[mt][nt], ah[mt], bl[nt]);   // hl
                    MMA16816F16(acc[mt][nt], al[mt], bh[nt]);   // lh
                }
        }
    };

    // ---- pipelined main loop over 8 K-chunks ----
    const int NCHUNK = D_ / 64;
    load_chunk(0, 0); CP_COMMIT();
    for (int kc = 0; kc < NCHUNK; ++kc) {
        if (kc + 1 < NCHUNK) {
            load_chunk(kc + 1, (kc + 1) & 1); CP_COMMIT();
            CP_WAIT(1);
        } else {
            CP_WAIT(0);
        }
        __syncthreads();
        compute_chunk(kc & 1);
        __syncthreads();                  // before next load overwrites other buf
    }

    // ---- epilogue: direct tile (coalesced float2 per fragment row) ----
    float* C = g_sim + (size_t)b * N_ * N_;
    int r0 = ti * 128 + wm * 32 + (lane >> 2);
    int c0 = tj * 128 + wn * 32 + (lane & 3) * 2;
    #pragma unroll
    for (int mt = 0; mt < 2; ++mt)
        #pragma unroll
        for (int nt = 0; nt < 4; ++nt) {
            float2 v01 = make_float2(acc[mt][nt][0], acc[mt][nt][1]);
            float2 v23 = make_float2(acc[mt][nt][2], acc[mt][nt][3]);
            *(float2*)(C + (size_t)(r0 + mt * 16) * N_ + c0 + nt * 8)     = v01;
            *(float2*)(C + (size_t)(r0 + mt * 16 + 8) * N_ + c0 + nt * 8) = v23;
        }

    // ---- mirror tile via smem transpose (coalesced write-out) ----
    if (ti != tj) {
        float* T = (float*)smem;          // [128][132] floats (67584 B)
        int rl = wm * 32 + (lane >> 2);
        int cl = wn * 32 + (lane & 3) * 2;
        #pragma unroll
        for (int mt = 0; mt < 2; ++mt)
            #pragma unroll
            for (int nt = 0; nt < 4; ++nt) {
                int rr = rl + mt * 16;
                int cc = cl + nt * 8;
                T[(size_t)(cc + 0) * 132 + rr]     = acc[mt][nt][0];
                T[(size_t)(cc + 1) * 132 + rr]     = acc[mt][nt][1];
                T[(size_t)(cc + 0) * 132 + rr + 8] = acc[mt][nt][2];
                T[(size_t)(cc + 1) * 132 + rr + 8] = acc[mt][nt][3];
            }
        __syncthreads();
        int jb = tj * 128, ib = ti * 128;
        #pragma unroll
        for (int q = 0; q < 8; ++q) {
            int uu = q * 512 + tid;       // 0..4095
            int r = uu >> 5;
            int c4 = uu & 31;
            float4 v = *(float4*)&T[(size_t)r * 132 + c4 * 4];
            *(float4*)(C + (size_t)(jb + r) * N_ + ib + c4 * 4) = v;
        }
    }
}

// ---------------------------------------------------------------------------
// Kernel 3: per-row top-32 + symmetric atomic scatter (unchanged).
// ---------------------------------------------------------------------------
__global__ void __launch_bounds__(256) topk_scatter_kernel(float* __restrict__ out) {
    int row = blockIdx.x;
    int b = row >> 12;
    int i = row & (N_ - 1);
    const float* srow = g_sim + (size_t)b * N_ * N_ + (size_t)i * N_;
    int t = threadIdx.x;
    int lane = t & 31, warp = t >> 5;

    const float NEG_INF = __int_as_float(0xff800000);

    float v[16];
    #pragma unroll
    for (int q = 0; q < 16; q++) v[q] = srow[warp * 512 + q * 32 + lane];

    __shared__ float cV[256];
    __shared__ int   cI[256];

    // ---- phase 1: per-warp top-32 (no block syncs) ----
    for (int r = 0; r < K_; r++) {
        float bv = v[0]; int bq = 0;
        #pragma unroll
        for (int q = 1; q < 16; q++)
            if (v[q] > bv) { bv = v[q]; bq = q; }
        int bix = warp * 512 + bq * 32 + lane;

        #pragma unroll
        for (int o = 16; o; o >>= 1) {
            float ov = __shfl_xor_sync(0xffffffffu, bv, o);
            int   oi = __shfl_xor_sync(0xffffffffu, bix, o);
            if (ov > bv || (ov == bv && oi < bix)) { bv = ov; bix = oi; }
        }
        if (lane == 0) { cV[warp * 32 + r] = bv; cI[warp * 32 + r] = bix; }
        if ((bix & 31) == lane) v[(bix >> 5) & 15] = NEG_INF;
    }
    __syncthreads();

    // ---- phase 2: warp 0 merges 256 candidates -> top-32 + scatter ----
    __shared__ float sV[K_];
    __shared__ int   sI[K_];
    if (warp == 0) {
        float cv[8]; int ci[8];
        #pragma unroll
        for (int j = 0; j < 8; j++) { cv[j] = cV[j * 32 + lane]; ci[j] = cI[j * 32 + lane]; }

        for (int r = 0; r < K_; r++) {
            float bv = cv[0]; int bi = ci[0];
            #pragma unroll
            for (int j = 1; j < 8; j++)
                if (cv[j] > bv || (cv[j] == bv && ci[j] < bi)) { bv = cv[j]; bi = ci[j]; }

            #pragma unroll
            for (int o = 16; o; o >>= 1) {
                float ov = __shfl_xor_sync(0xffffffffu, bv, o);
                int   oi = __shfl_xor_sync(0xffffffffu, bi, o);
                if (ov > bv || (ov == bv && oi < bi)) { bv = ov; bi = oi; }
            }
            if (lane == 0) { sV[r] = bv; sI[r] = bi; }
            #pragma unroll
            for (int j = 0; j < 8; j++)
                if (ci[j] == bi) cv[j] = NEG_INF;
        }
    }
    __syncthreads();

    if (t < K_) {
        float val = 0.5f * sV[t];
        int j = sI[t];
        float* ob = out + (size_t)b * N_ * N_;
        atomicAdd(ob + (size_t)i * N_ + j, val);
        atomicAdd(ob + (size_t)j * N_ + i, val);
    }
}

// ---------------------------------------------------------------------------
extern "C" void kernel_launch(void* const* d_in, const int* in_sizes, int n_in,
                              void* d_out, int out_size) {
    const float* x = (const float*)d_in[0];
    float* out = (float*)d_out;

    cudaFuncSetAttribute(gemm_hmma_kernel,
                         cudaFuncAttributeMaxDynamicSharedMemorySize, SMEM_TOTAL);

    cudaMemsetAsync(out, 0, (size_t)out_size * sizeof(float));
    normalize_kernel<<<B_ * N_, 128>>>(x);
    gemm_hmma_kernel<<<B_ * PAIRS, 512, SMEM_TOTAL>>>();
    topk_scatter_kernel<<<B_ * N_, 256>>>(out);
}